// round 14
// baseline (speedup 1.0000x reference)
#include <cuda_runtime.h>

#define T_STEPS 8192
#define IDIM 256
#define HDIM 1024
#define NBLOCKS 128
#define NTHREADS 256       // 8 warps; warp w handles h index j = 8*block + w
#define NAN_BITS 0x7fc00000u

// h history: row t holds h_{t-1} (input to step t). Row 0 = zeros (h_0).
// Rows 1..T start as sentinel NaN. Each element is written EXACTLY ONCE,
// so any non-sentinel read is the final value — the validated load IS the
// synchronization. h = o*tanh(c) ∈ (-1,1) never equals the sentinel.
__device__ __align__(16) float g_hs[(T_STEPS + 1) * HDIM];

__global__ void init_kernel() {
    unsigned int v = (blockIdx.x == 0) ? 0u : NAN_BITS;
    uint4 q = make_uint4(v, v, v, v);
    reinterpret_cast<uint4*>(g_hs + (size_t)blockIdx.x * HDIM)[threadIdx.x] = q;
}

__device__ __forceinline__ float sigmoid_fast(float x) {
    return 1.0f / (1.0f + __expf(-x));
}
// Packed dual-FMA: d.xy += a.xy * b.xy  (Blackwell f32x2, PTX-only)
__device__ __forceinline__ void fma2(unsigned long long& d,
                                     unsigned long long a,
                                     unsigned long long b) {
    asm("fma.rn.f32x2 %0, %1, %2, %0;" : "+l"(d) : "l"(a), "l"(b));
}
__device__ __forceinline__ unsigned long long ld64(const float* p) {
    return *reinterpret_cast<const unsigned long long*>(p);
}
__device__ __forceinline__ unsigned long long pack2(unsigned int x, unsigned int y) {
    unsigned long long d;
    asm("mov.b64 %0, {%1,%2};" : "=l"(d) : "r"(x), "r"(y));
    return d;
}
__device__ __forceinline__ float pairsum(unsigned long long v) {
    float2 f = *reinterpret_cast<float2*>(&v);
    return f.x + f.y;
}

__global__ void __launch_bounds__(NTHREADS, 1)
lstm_kernel(const float* __restrict__ seq,
            const float* __restrict__ W_ih,
            const float* __restrict__ W_hh,
            const float* __restrict__ b_ih,
            const float* __restrict__ b_hh)
{
    __shared__ __align__(16) float h_s[HDIM];   // single buffer (R9 frame)

    const int tid  = threadIdx.x;
    const int warp = tid >> 5;
    const int lane = tid & 31;
    const int j    = blockIdx.x * 8 + warp;     // h index this warp owns
    const int gate = lane & 3;
    const int col  = 4 * lane;                  // lane owns cols 4L+128m..+3

    const int r0 = j;
    const int r1 = j + HDIM;
    const int r2 = j + 2 * HDIM;
    const int r3 = j + 3 * HDIM;

    // ---- Recurrent weights, register-resident; column map matches the
    // LDS.128 read pattern: pairs (4L+128m, +1) and (4L+128m+2, +3). ----
    unsigned long long whl0[8], whh0[8], whl1[8], whh1[8];
    unsigned long long whl2[8], whh2[8], whl3[8], whh3[8];
    #pragma unroll
    for (int m = 0; m < 8; m++) {
        const float* b0 = W_hh + (size_t)r0 * HDIM + col + 128 * m;
        const float* b1 = W_hh + (size_t)r1 * HDIM + col + 128 * m;
        const float* b2 = W_hh + (size_t)r2 * HDIM + col + 128 * m;
        const float* b3 = W_hh + (size_t)r3 * HDIM + col + 128 * m;
        whl0[m] = ld64(b0); whh0[m] = ld64(b0 + 2);
        whl1[m] = ld64(b1); whh1[m] = ld64(b1 + 2);
        whl2[m] = ld64(b2); whh2[m] = ld64(b2 + 2);
        whl3[m] = ld64(b3); whh3[m] = ld64(b3 + 2);
    }
    // ---- Input-projection weights, same map (m = 0..1). ----
    unsigned long long wxl0[2], wxh0[2], wxl1[2], wxh1[2];
    unsigned long long wxl2[2], wxh2[2], wxl3[2], wxh3[2];
    #pragma unroll
    for (int m = 0; m < 2; m++) {
        const float* b0 = W_ih + (size_t)r0 * IDIM + col + 128 * m;
        const float* b1 = W_ih + (size_t)r1 * IDIM + col + 128 * m;
        const float* b2 = W_ih + (size_t)r2 * IDIM + col + 128 * m;
        const float* b3 = W_ih + (size_t)r3 * IDIM + col + 128 * m;
        wxl0[m] = ld64(b0); wxh0[m] = ld64(b0 + 2);
        wxl1[m] = ld64(b1); wxh1[m] = ld64(b1 + 2);
        wxl2[m] = ld64(b2); wxh2[m] = ld64(b2 + 2);
        wxl3[m] = ld64(b3); wxh3[m] = ld64(b3 + 2);
    }

    // Per-lane bias + activation constants (one-exp trick, R9-proven).
    const int brow = j + gate * HDIM;
    const float bias_lane = b_ih[brow] + b_hh[brow];
    const float pre   = (gate == 2) ? -2.0f : -1.0f;
    const float postA = (gate == 2) ?  2.0f :  1.0f;
    const float postB = (gate == 2) ? -1.0f :  0.0f;

    // x_t, prefetched one step ahead as two LDG.128.
    uint4 xq0 = *reinterpret_cast<const uint4*>(seq + col);
    uint4 xq1 = *reinterpret_cast<const uint4*>(seq + col + 128);

    float c_state = 0.0f;

    #pragma unroll 1
    for (int t = 0; t < T_STEPS; ++t) {
        // ---- Prime ONE poll load before any compute (same traffic as R9;
        // if data isn't ready yet this degenerates to exactly R9 timing). ----
        const float* p = g_hs + (size_t)t * HDIM + 128 * warp + col;
        unsigned int v0, v1, v2, v3;
        asm volatile("ld.global.cg.v4.b32 {%0,%1,%2,%3}, [%4];"
                     : "=r"(v0), "=r"(v1), "=r"(v2), "=r"(v3) : "l"(p));

        // ---- x-projection in the prime's shadow. ----
        unsigned long long a0 = 0, a1 = 0, a2 = 0, a3 = 0;
        {
            unsigned long long xl0 = pack2(xq0.x, xq0.y), xh0 = pack2(xq0.z, xq0.w);
            unsigned long long xl1 = pack2(xq1.x, xq1.y), xh1 = pack2(xq1.z, xq1.w);
            fma2(a0, wxl0[0], xl0); fma2(a0, wxh0[0], xh0);
            fma2(a1, wxl1[0], xl0); fma2(a1, wxh1[0], xh0);
            fma2(a2, wxl2[0], xl0); fma2(a2, wxh2[0], xh0);
            fma2(a3, wxl3[0], xl0); fma2(a3, wxh3[0], xh0);
            fma2(a0, wxl0[1], xl1); fma2(a0, wxh0[1], xh1);
            fma2(a1, wxl1[1], xl1); fma2(a1, wxh1[1], xh1);
            fma2(a2, wxl2[1], xl1); fma2(a2, wxh2[1], xh1);
            fma2(a3, wxl3[1], xl1); fma2(a3, wxh3[1], xh1);
        }

        // ---- Sticky vote-poll (R9 structure: ONE load in flight, uniform
        // __all_sync exit — divergent spin exits NaN on sm_103a). ----
        int ok = (v0 != NAN_BITS) & (v1 != NAN_BITS) &
                 (v2 != NAN_BITS) & (v3 != NAN_BITS);
        while (!__all_sync(0xffffffffu, ok)) {
            if (!ok) {
                asm volatile("ld.global.cg.v4.b32 {%0,%1,%2,%3}, [%4];"
                             : "=r"(v0), "=r"(v1), "=r"(v2), "=r"(v3) : "l"(p));
                ok = (v0 != NAN_BITS) & (v1 != NAN_BITS) &
                     (v2 != NAN_BITS) & (v3 != NAN_BITS);
            }
        }

        // Stage this warp's segment (chunk == column group: same layout).
        reinterpret_cast<uint4*>(h_s)[tid] = make_uint4(v0, v1, v2, v3);
        __syncthreads();

        // ---- Recurrent matvec: one LDS.128 per 128-col group (conflict-free
        // contiguous 512B per warp), two fma2 per gate per group. ----
        #pragma unroll
        for (int m = 0; m < 8; m++) {
            uint4 hv = *reinterpret_cast<const uint4*>(h_s + col + 128 * m);
            unsigned long long lo = pack2(hv.x, hv.y);
            unsigned long long hi = pack2(hv.z, hv.w);
            fma2(a0, whl0[m], lo); fma2(a0, whh0[m], hi);
            fma2(a1, whl1[m], lo); fma2(a1, whh1[m], hi);
            fma2(a2, whl2[m], lo); fma2(a2, whh2[m], hi);
            fma2(a3, whl3[m], lo); fma2(a3, whh3[m], hi);
        }

        float s0 = pairsum(a0), s1 = pairsum(a1),
              s2 = pairsum(a2), s3 = pairsum(a3);

        // ---- Merged reduction (R9-proven). ----
        {
            bool hi = (lane & 1);
            float keep01 = hi ? s1 : s0, send01 = hi ? s0 : s1;
            float keep23 = hi ? s3 : s2, send23 = hi ? s2 : s3;
            s0 = keep01 + __shfl_xor_sync(0xffffffffu, send01, 1);
            s2 = keep23 + __shfl_xor_sync(0xffffffffu, send23, 1);
        }
        float w;
        {
            bool hi = (lane & 2);
            float keep = hi ? s2 : s0, send = hi ? s0 : s2;
            w = keep + __shfl_xor_sync(0xffffffffu, send, 2);
        }
        w += __shfl_xor_sync(0xffffffffu, w, 4);
        w += __shfl_xor_sync(0xffffffffu, w, 8);
        w += __shfl_xor_sync(0xffffffffu, w, 16);

        // ---- ONE nonlinearity for all gates; gather; cell; publish ASAP
        // (lane 0 STG immediately after the cell — law #3). ----
        float act = fmaf(postA,
                         1.0f / (1.0f + __expf(pre * (w + bias_lane))),
                         postB);
        float i_ = __shfl_sync(0xffffffffu, act, 0);
        float f_ = __shfl_sync(0xffffffffu, act, 1);
        float g_ = __shfl_sync(0xffffffffu, act, 2);
        float o_ = __shfl_sync(0xffffffffu, act, 3);

        c_state = f_ * c_state + i_ * g_;
        float tc = fmaf(2.0f, 1.0f / (1.0f + __expf(-2.0f * c_state)), -1.0f);
        float h_ = o_ * tc;
        if (lane == 0) {
            asm volatile("st.global.cg.f32 [%0], %1;"
                         :: "l"(g_hs + (size_t)(t + 1) * HDIM + j), "f"(h_));
        }

        // ---- Prefetch x_{t+1}; hides behind the barrier + next poll. ----
        if (t + 1 < T_STEPS) {
            const float* xrow = seq + (size_t)(t + 1) * IDIM + col;
            xq0 = *reinterpret_cast<const uint4*>(xrow);
            xq1 = *reinterpret_cast<const uint4*>(xrow + 128);
        }

        __syncthreads();    // trailing barrier (R9 frame): parks warps at BAR,
                            // keeping chip-wide poll traffic under the LTS cap.
    }
}

// out[t] = sigmoid(h_{t+1} . W_out + b_out); one warp per timestep.
__global__ void __launch_bounds__(256)
out_kernel(const float* __restrict__ W_out,
           const float* __restrict__ b_out,
           float* __restrict__ out)
{
    const int warp = threadIdx.x >> 5;
    const int lane = threadIdx.x & 31;
    const int t = blockIdx.x * 8 + warp;
    if (t >= T_STEPS) return;

    const float* hrow = g_hs + (size_t)(t + 1) * HDIM;
    float acc = 0.0f;
    #pragma unroll
    for (int k = 0; k < 32; k++) {
        int c = lane + 32 * k;
        acc = fmaf(hrow[c], W_out[c], acc);
    }
    #pragma unroll
    for (int off = 16; off > 0; off >>= 1)
        acc += __shfl_xor_sync(0xffffffffu, acc, off);
    if (lane == 0)
        out[t] = sigmoid_fast(acc + b_out[0]);
}

extern "C" void kernel_launch(void* const* d_in, const int* in_sizes, int n_in,
                              void* d_out, int out_size)
{
    const float* seq   = (const float*)d_in[0];   // [8192, 256]
    const float* W_ih  = (const float*)d_in[1];   // [4096, 256]
    const float* W_hh  = (const float*)d_in[2];   // [4096, 1024]
    const float* b_ih  = (const float*)d_in[3];   // [4096]
    const float* b_hh  = (const float*)d_in[4];   // [4096]
    const float* W_out = (const float*)d_in[5];   // [1, 1024]
    const float* b_out = (const float*)d_in[6];   // [1]
    float* out = (float*)d_out;                   // [8192, 1]

    init_kernel<<<T_STEPS + 1, NTHREADS>>>();
    lstm_kernel<<<NBLOCKS, NTHREADS>>>(seq, W_ih, W_hh, b_ih, b_hh);
    out_kernel<<<T_STEPS / 8, 256>>>(W_out, b_out, out);
}

// round 15
// speedup vs baseline: 1.9503x; 1.9503x over previous
#include <cuda_runtime.h>

#define T_STEPS 8192
#define IDIM 256
#define HDIM 1024
#define NBLOCKS 128
#define NTHREADS 256       // 8 warps; warp w handles h index j = 8*block + w
#define NAN_BITS 0x7fc00000u
#define NREP 4
#define REP_STRIDE ((size_t)(T_STEPS + 1) * HDIM)

// h history, REPLICATED 4x to spread poll traffic across L2 slices and cut
// same-address contention (128 -> 32 pollers per address). Row t of each
// replica holds h_{t-1}. Rows 1..T start as sentinel NaN; each element is
// written EXACTLY ONCE, so any non-sentinel read is final — the validated
// load IS the synchronization. h = o*tanh(c) ∈ (-1,1) never hits the sentinel.
__device__ __align__(16) float g_hs[NREP * (T_STEPS + 1) * HDIM];

// One block per (replica, row): zeros for t==0, sentinel otherwise.
__global__ void init_kernel() {
    int row = blockIdx.x % (T_STEPS + 1);
    unsigned int v = (row == 0) ? 0u : NAN_BITS;
    uint4 q = make_uint4(v, v, v, v);
    reinterpret_cast<uint4*>(g_hs + (size_t)blockIdx.x * HDIM)[threadIdx.x] = q;
}

__device__ __forceinline__ float sigmoid_fast(float x) {
    return 1.0f / (1.0f + __expf(-x));
}
// Packed dual-FMA: d.xy += a.xy * b.xy  (Blackwell f32x2, PTX-only)
__device__ __forceinline__ void fma2(unsigned long long& d,
                                     unsigned long long a,
                                     unsigned long long b) {
    asm("fma.rn.f32x2 %0, %1, %2, %0;" : "+l"(d) : "l"(a), "l"(b));
}
__device__ __forceinline__ unsigned long long ld64(const float* p) {
    return *reinterpret_cast<const unsigned long long*>(p);
}
__device__ __forceinline__ float pairsum(unsigned long long v) {
    float2 f = *reinterpret_cast<float2*>(&v);
    return f.x + f.y;
}

__global__ void __launch_bounds__(NTHREADS, 1)
lstm_kernel(const float* __restrict__ seq,
            const float* __restrict__ W_ih,
            const float* __restrict__ W_hh,
            const float* __restrict__ b_ih,
            const float* __restrict__ b_hh)
{
    __shared__ __align__(16) float h_s[HDIM];   // single buffer (R9 frame)

    const int tid  = threadIdx.x;
    const int warp = tid >> 5;
    const int lane = tid & 31;
    const int j    = blockIdx.x * 8 + warp;     // h index this warp owns
    const int gate = lane & 3;

    const int r0 = j;
    const int r1 = j + HDIM;
    const int r2 = j + 2 * HDIM;
    const int r3 = j + 3 * HDIM;

    // ---- Recurrent weights, register-resident as f32x2 pairs (R9 layout). ----
    unsigned long long wh0[16], wh1[16], wh2[16], wh3[16];
    #pragma unroll
    for (int k = 0; k < 16; k++) {
        wh0[k] = ld64(W_hh + (size_t)r0 * HDIM + 2 * lane + 64 * k);
        wh1[k] = ld64(W_hh + (size_t)r1 * HDIM + 2 * lane + 64 * k);
        wh2[k] = ld64(W_hh + (size_t)r2 * HDIM + 2 * lane + 64 * k);
        wh3[k] = ld64(W_hh + (size_t)r3 * HDIM + 2 * lane + 64 * k);
    }
    // ---- Input-projection weights. ----
    unsigned long long wx0[4], wx1[4], wx2[4], wx3[4];
    #pragma unroll
    for (int k = 0; k < 4; k++) {
        wx0[k] = ld64(W_ih + (size_t)r0 * IDIM + 2 * lane + 64 * k);
        wx1[k] = ld64(W_ih + (size_t)r1 * IDIM + 2 * lane + 64 * k);
        wx2[k] = ld64(W_ih + (size_t)r2 * IDIM + 2 * lane + 64 * k);
        wx3[k] = ld64(W_ih + (size_t)r3 * IDIM + 2 * lane + 64 * k);
    }

    // Per-lane bias + activation constants (one-exp trick, R9-proven).
    const int brow = j + gate * HDIM;
    const float bias_lane = b_ih[brow] + b_hh[brow];
    const float pre   = (gate == 2) ? -2.0f : -1.0f;
    const float postA = (gate == 2) ?  2.0f :  1.0f;
    const float postB = (gate == 2) ? -1.0f :  0.0f;

    // x_t pairs, prefetched one step ahead (R9 layout).
    unsigned long long xr[4];
    #pragma unroll
    for (int k = 0; k < 4; k++)
        xr[k] = ld64(seq + 2 * lane + 64 * k);

    // This block polls its own replica; producers feed all replicas.
    float* const my_rep = g_hs + (size_t)(blockIdx.x & (NREP - 1)) * REP_STRIDE;

    float c_state = 0.0f;

    #pragma unroll 1
    for (int t = 0; t < T_STEPS; ++t) {
        // ---- x-projection FIRST (R9 order — law #4: do not issue the poll
        // earlier than this frame does). ----
        unsigned long long a0 = 0, a1 = 0, a2 = 0, a3 = 0;
        #pragma unroll
        for (int k = 0; k < 4; k++) {
            fma2(a0, wx0[k], xr[k]);
            fma2(a1, wx1[k], xr[k]);
            fma2(a2, wx2[k], xr[k]);
            fma2(a3, wx3[k], xr[k]);
        }

        // ---- Sticky vote-poll on own replica (R9 structure: first load
        // in-loop, ONE load in flight, uniform __all_sync exit). ----
        const float* p = my_rep + (size_t)t * HDIM + 128 * warp + 4 * lane;
        unsigned int v0, v1, v2, v3;
        int ok = 0;
        do {
            if (!ok) {
                asm volatile("ld.global.cg.v4.b32 {%0,%1,%2,%3}, [%4];"
                             : "=r"(v0), "=r"(v1), "=r"(v2), "=r"(v3) : "l"(p));
                ok = (v0 != NAN_BITS) & (v1 != NAN_BITS) &
                     (v2 != NAN_BITS) & (v3 != NAN_BITS);
            }
        } while (!__all_sync(0xffffffffu, ok));

        // Stage this warp's segment.
        reinterpret_cast<uint4*>(h_s)[tid] = make_uint4(v0, v1, v2, v3);
        __syncthreads();

        // ---- Recurrent matvec, SPLIT HALVES: half A (k=0..7) accumulates
        // into a*, then A's pairsum+merge shuffles (MIO pipe) overlap half
        // B's fma2 issue (FMA pipe). ----
        #pragma unroll
        for (int k = 0; k < 8; k++) {
            unsigned long long hv = ld64(h_s + 2 * lane + 64 * k);
            fma2(a0, wh0[k], hv);
            fma2(a1, wh1[k], hv);
            fma2(a2, wh2[k], hv);
            fma2(a3, wh3[k], hv);
        }
        float s0a = pairsum(a0), s1a = pairsum(a1),
              s2a = pairsum(a2), s3a = pairsum(a3);
        float wa;
        {
            bool hi = (lane & 1);
            float keep01 = hi ? s1a : s0a, send01 = hi ? s0a : s1a;
            float keep23 = hi ? s3a : s2a, send23 = hi ? s2a : s3a;
            float m01 = keep01 + __shfl_xor_sync(0xffffffffu, send01, 1);
            float m23 = keep23 + __shfl_xor_sync(0xffffffffu, send23, 1);
            bool hi2 = (lane & 2);
            float keep = hi2 ? m23 : m01, send = hi2 ? m01 : m23;
            wa = keep + __shfl_xor_sync(0xffffffffu, send, 2);
        }

        unsigned long long b0 = 0, b1 = 0, b2 = 0, b3 = 0;
        #pragma unroll
        for (int k = 8; k < 16; k++) {
            unsigned long long hv = ld64(h_s + 2 * lane + 64 * k);
            fma2(b0, wh0[k], hv);
            fma2(b1, wh1[k], hv);
            fma2(b2, wh2[k], hv);
            fma2(b3, wh3[k], hv);
        }
        float s0b = pairsum(b0), s1b = pairsum(b1),
              s2b = pairsum(b2), s3b = pairsum(b3);
        float wb;
        {
            bool hi = (lane & 1);
            float keep01 = hi ? s1b : s0b, send01 = hi ? s0b : s1b;
            float keep23 = hi ? s3b : s2b, send23 = hi ? s2b : s3b;
            float m01 = keep01 + __shfl_xor_sync(0xffffffffu, send01, 1);
            float m23 = keep23 + __shfl_xor_sync(0xffffffffu, send23, 1);
            bool hi2 = (lane & 2);
            float keep = hi2 ? m23 : m01, send = hi2 ? m01 : m23;
            wb = keep + __shfl_xor_sync(0xffffffffu, send, 2);
        }

        // Combine halves, then one 3-stage butterfly over 8-lane groups.
        float w = wa + wb;
        w += __shfl_xor_sync(0xffffffffu, w, 4);
        w += __shfl_xor_sync(0xffffffffu, w, 8);
        w += __shfl_xor_sync(0xffffffffu, w, 16);

        // ---- ONE nonlinearity for all gates; gather; cell; publish ASAP. ----
        float act = fmaf(postA,
                         1.0f / (1.0f + __expf(pre * (w + bias_lane))),
                         postB);
        float i_ = __shfl_sync(0xffffffffu, act, 0);
        float f_ = __shfl_sync(0xffffffffu, act, 1);
        float g_ = __shfl_sync(0xffffffffu, act, 2);
        float o_ = __shfl_sync(0xffffffffu, act, 3);

        c_state = f_ * c_state + i_ * g_;
        float tc = fmaf(2.0f, 1.0f / (1.0f + __expf(-2.0f * c_state)), -1.0f);
        float h_ = o_ * tc;
        // h_ is uniform across lanes: lanes 0-3 publish to the 4 replicas in
        // parallel — same publish instant as R9's single store (law #3).
        if (lane < NREP) {
            asm volatile("st.global.cg.f32 [%0], %1;"
                         :: "l"(g_hs + (size_t)lane * REP_STRIDE
                                 + (size_t)(t + 1) * HDIM + j), "f"(h_));
        }

        // ---- Prefetch x_{t+1}; hides behind the next poll. ----
        if (t + 1 < T_STEPS) {
            const float* xrow = seq + (size_t)(t + 1) * IDIM + 2 * lane;
            #pragma unroll
            for (int k = 0; k < 4; k++)
                xr[k] = ld64(xrow + 64 * k);
        }

        __syncthreads();    // trailing barrier (R9 frame): parks warps at BAR,
                            // keeping chip-wide poll traffic under the LTS cap.
    }
}

// out[t] = sigmoid(h_{t+1} . W_out + b_out); one warp per timestep.
// Reads replica 0 (written by lane 0).
__global__ void __launch_bounds__(256)
out_kernel(const float* __restrict__ W_out,
           const float* __restrict__ b_out,
           float* __restrict__ out)
{
    const int warp = threadIdx.x >> 5;
    const int lane = threadIdx.x & 31;
    const int t = blockIdx.x * 8 + warp;
    if (t >= T_STEPS) return;

    const float* hrow = g_hs + (size_t)(t + 1) * HDIM;
    float acc = 0.0f;
    #pragma unroll
    for (int k = 0; k < 32; k++) {
        int c = lane + 32 * k;
        acc = fmaf(hrow[c], W_out[c], acc);
    }
    #pragma unroll
    for (int off = 16; off > 0; off >>= 1)
        acc += __shfl_xor_sync(0xffffffffu, acc, off);
    if (lane == 0)
        out[t] = sigmoid_fast(acc + b_out[0]);
}

extern "C" void kernel_launch(void* const* d_in, const int* in_sizes, int n_in,
                              void* d_out, int out_size)
{
    const float* seq   = (const float*)d_in[0];   // [8192, 256]
    const float* W_ih  = (const float*)d_in[1];   // [4096, 256]
    const float* W_hh  = (const float*)d_in[2];   // [4096, 1024]
    const float* b_ih  = (const float*)d_in[3];   // [4096]
    const float* b_hh  = (const float*)d_in[4];   // [4096]
    const float* W_out = (const float*)d_in[5];   // [1, 1024]
    const float* b_out = (const float*)d_in[6];   // [1]
    float* out = (float*)d_out;                   // [8192, 1]

    init_kernel<<<NREP * (T_STEPS + 1), NTHREADS>>>();
    lstm_kernel<<<NBLOCKS, NTHREADS>>>(seq, W_ih, W_hh, b_ih, b_hh);
    out_kernel<<<T_STEPS / 8, 256>>>(W_out, b_out, out);
}